// round 7
// baseline (speedup 1.0000x reference)
#include <cuda_runtime.h>
#include <math.h>

// Problem constants
constexpr int H_ = 1024;
constexpr int G_ = 4096;   // 4*H
constexpr int B_ = 32;
constexpr int T_ = 64;
constexpr int S_ = 64;
constexpr int L_ = 2;

// GEMM tiling
constexpr int KT  = 128;            // K tile
constexpr int XST = 132;            // padded smem row stride (words)
constexpr int XB  = B_ * XST;       // x tile floats (4224)
constexpr int WBMAX = 32 * XST;     // w tile floats, 32 rows max (4224)
constexpr int SMEM_STEPS = (2 * XB + 2 * WBMAX) * 4;   // 67584 B (persistent kernel)

constexpr int WB128 = 16 * XST;     // pre0 (128-thread) w tile
constexpr int SMEM_PRE0 = (2 * XB + 2 * WB128) * 4;    // 50688 B

constexpr int NBLK = 128;           // persistent grid (<=148 SMs, all co-resident)

// Scratch (device globals)
__device__ float g_pre0[(size_t)T_ * G_ * B_];   // [t][j][b]
__device__ float g_hbuf[2][L_][B_][H_];          // ping-pong h state
__device__ float g_c[L_][B_][H_];                // c state
__device__ float g_gamma[B_][H_];
__device__ float g_ctx[B_][H_];

// grid barrier state
__device__ unsigned g_bar_cnt;
__device__ volatile unsigned g_bar_gen;

__device__ __forceinline__ float sigf(float x) { return 1.f / (1.f + expf(-x)); }

__device__ __forceinline__ unsigned su32(const void* p) {
    return (unsigned)__cvta_generic_to_shared(p);
}
#define CPA16(d, s) asm volatile("cp.async.ca.shared.global [%0], [%1], 16;" :: "r"(d), "l"(s) : "memory")
#define CP_COMMIT() asm volatile("cp.async.commit_group;" ::: "memory")

__device__ __forceinline__ float unpack_sum(unsigned long long u) {
    float lo, hi;
    asm("mov.b64 {%0,%1}, %2;" : "=f"(lo), "=f"(hi) : "l"(u));
    return lo + hi;
}

// Grid-wide barrier (canonical fence + atomicInc + spin; all NBLK CTAs resident)
__device__ __forceinline__ void grid_bar() {
    __syncthreads();
    if (threadIdx.x == 0) {
        __threadfence();
        unsigned gen = g_bar_gen;
        if (atomicInc(&g_bar_cnt, NBLK - 1) == NBLK - 1) {
            g_bar_gen = gen + 1;           // release new generation
        } else {
            while (g_bar_gen == gen) { __nanosleep(128); }
        }
        __threadfence();
    }
    __syncthreads();
}

// ===========================================================================
// 256-thread GEMM machinery (persistent step kernel)
// Row map for smem row rr in [0, 8*NR): row = rowBase + (rr%NR)*sg + (rr/NR)*sc
// Warp wid computes smem rows wid*NR .. wid*NR+NR-1, lane = batch.
// ===========================================================================
__device__ __forceinline__ void stage_x256(float* xsb, const float* __restrict__ X, int tid) {
#pragma unroll
    for (int i = tid; i < B_ * (KT / 4); i += 256) {
        int b = i >> 5, k4 = i & 31;
        CPA16(su32(xsb + b * XST + k4 * 4), X + (size_t)b * H_ + k4 * 4);
    }
}
template <int NR>
__device__ __forceinline__ void stage_w256(float* wsb, const float* __restrict__ Wk0,
                                           size_t ldw, int rowBase, int sg, int sc, int tid) {
#pragma unroll
    for (int i = tid; i < 8 * NR * (KT / 4); i += 256) {
        int rr = i >> 5, k4 = i & 31;
        int row = rowBase + (rr % NR) * sg + (rr / NR) * sc;
        CPA16(su32(wsb + rr * XST + k4 * 4), Wk0 + (size_t)row * ldw + k4 * 4);
    }
}
template <int NR>
__device__ __forceinline__ void comp256(const float* xsb, const float* wsb,
                                        unsigned long long* acc, int wid, int lane) {
    const float* xp = xsb + lane * XST;
    const float* wp = wsb + wid * NR * XST;
#pragma unroll 4
    for (int k = 0; k < KT; k += 4) {
        ulonglong2 xv = *(const ulonglong2*)(xp + k);
#pragma unroll
        for (int r = 0; r < NR; r++) {
            ulonglong2 wv = *(const ulonglong2*)(wp + r * XST + k);
            asm("fma.rn.f32x2 %0, %1, %2, %0;" : "+l"(acc[r]) : "l"(xv.x), "l"(wv.x));
            asm("fma.rn.f32x2 %0, %1, %2, %0;" : "+l"(acc[r]) : "l"(xv.y), "l"(wv.y));
        }
    }
}
template <int NR>
__device__ __forceinline__ void gemm_seg256(float* sm, const float* __restrict__ X,
                                            const float* __restrict__ W, size_t ldw,
                                            int rowBase, int sg, int sc,
                                            unsigned long long* acc,
                                            int tid, int wid, int lane) {
    float* xs = sm;
    float* ws = sm + 2 * XB;
    stage_x256(xs, X, tid);
    stage_w256<NR>(ws, W, ldw, rowBase, sg, sc, tid);
    CP_COMMIT();
    constexpr int NT = H_ / KT;   // 8
    for (int t = 0; t < NT; t++) {
        const int cb = t & 1;
        if (t + 1 < NT) {
            const int nb = cb ^ 1;
            stage_x256(xs + nb * XB, X + (t + 1) * KT, tid);
            stage_w256<NR>(ws + nb * WBMAX, W + (size_t)(t + 1) * KT, ldw, rowBase, sg, sc, tid);
            CP_COMMIT();
            asm volatile("cp.async.wait_group 1;" ::: "memory");
        } else {
            asm volatile("cp.async.wait_group 0;" ::: "memory");
        }
        __syncthreads();
        comp256<NR>(xs + cb * XB, ws + cb * WBMAX, acc, wid, lane);
        __syncthreads();
    }
}

// ===========================================================================
// Persistent kernel: whole T-loop. grid = NBLK x 256 threads.
// Per step: cell0 | BAR | cell1 | BAR | gamma | BAR | attn | BAR | out
// (no barrier after out: its inputs are protected by the next 3 barriers)
// ===========================================================================
__global__ void __launch_bounds__(256) k_steps(const float* __restrict__ Whh0,
                                               const float* __restrict__ Wih1,
                                               const float* __restrict__ Whh1,
                                               const float* __restrict__ bih1,
                                               const float* __restrict__ bhh1,
                                               const float* __restrict__ W_in,
                                               const float* __restrict__ b_in,
                                               const float* __restrict__ W_out,
                                               const float* __restrict__ b_out,
                                               const float* __restrict__ contexts,
                                               float* __restrict__ out) {
    extern __shared__ float sm[];
    __shared__ float gs[H_];
    __shared__ float w_sh[S_];
    const int tid = threadIdx.x, wid = tid >> 5, lane = tid & 31;
    const int blk = blockIdx.x;

    for (int t = 0; t < T_; t++) {
        const int cur = t & 1;

        // ---- cell0: j = blk*8 + wid, gates r=0..3 at rows j + r*H ----
        {
            unsigned long long acc[4] = {0ull, 0ull, 0ull, 0ull};
            gemm_seg256<4>(sm, &g_hbuf[1 - cur][0][0][0], Whh0, H_,
                           blk * 8, H_, 1, acc, tid, wid, lane);
            const int j = blk * 8 + wid;
            const float* pre = g_pre0 + (size_t)t * G_ * B_;
            float a_i = unpack_sum(acc[0]) + pre[(size_t)(0 * H_ + j) * B_ + lane];
            float a_f = unpack_sum(acc[1]) + pre[(size_t)(1 * H_ + j) * B_ + lane];
            float a_g = unpack_sum(acc[2]) + pre[(size_t)(2 * H_ + j) * B_ + lane];
            float a_o = unpack_sum(acc[3]) + pre[(size_t)(3 * H_ + j) * B_ + lane];
            float c1 = sigf(a_f) * g_c[0][lane][j] + sigf(a_i) * tanhf(a_g);
            g_c[0][lane][j] = c1;
            g_hbuf[cur][0][lane][j] = sigf(a_o) * tanhf(c1);
        }
        grid_bar();

        // ---- cell1: gates = h0_cur@Wih1^T + h1_prev@Whh1^T + biases ----
        {
            unsigned long long acc[4] = {0ull, 0ull, 0ull, 0ull};
            gemm_seg256<4>(sm, &g_hbuf[cur][0][0][0], Wih1, H_,
                           blk * 8, H_, 1, acc, tid, wid, lane);
            gemm_seg256<4>(sm, &g_hbuf[1 - cur][1][0][0], Whh1, H_,
                           blk * 8, H_, 1, acc, tid, wid, lane);
            const int j = blk * 8 + wid;
            float a_i = unpack_sum(acc[0]) + bih1[0 * H_ + j] + bhh1[0 * H_ + j];
            float a_f = unpack_sum(acc[1]) + bih1[1 * H_ + j] + bhh1[1 * H_ + j];
            float a_g = unpack_sum(acc[2]) + bih1[2 * H_ + j] + bhh1[2 * H_ + j];
            float a_o = unpack_sum(acc[3]) + bih1[3 * H_ + j] + bhh1[3 * H_ + j];
            float c1 = sigf(a_f) * g_c[1][lane][j] + sigf(a_i) * tanhf(a_g);
            g_c[1][lane][j] = c1;
            g_hbuf[cur][1][lane][j] = sigf(a_o) * tanhf(c1);
        }
        grid_bar();

        // ---- gamma = h1 @ W_in^T + b_in: row j = blk*8 + wid ----
        {
            unsigned long long acc[1] = {0ull};
            gemm_seg256<1>(sm, &g_hbuf[cur][1][0][0], W_in, H_,
                           blk * 8, 0, 1, acc, tid, wid, lane);
            const int j = blk * 8 + wid;
            g_gamma[lane][j] = unpack_sum(acc[0]) + b_in[j];
        }
        grid_bar();

        // ---- attention: blocks 0..31, b = blk ----
        if (blk < B_) {
            const int b = blk;
            for (int i = tid; i < H_; i += 256) gs[i] = g_gamma[b][i];
            __syncthreads();
#pragma unroll
            for (int si = 0; si < S_ / 8; si++) {
                int s = wid * (S_ / 8) + si;
                const float* cp = contexts + ((size_t)b * S_ + s) * H_;
                float a = 0.f;
                for (int k = lane; k < H_; k += 32) a = fmaf(cp[k], gs[k], a);
#pragma unroll
                for (int o = 16; o; o >>= 1) a += __shfl_xor_sync(0xffffffffu, a, o);
                if (lane == 0) w_sh[s] = a;
            }
            __syncthreads();
            if (wid == 0) {
                float v0 = w_sh[lane], v1 = w_sh[lane + 32];
                float m = fmaxf(v0, v1);
#pragma unroll
                for (int o = 16; o; o >>= 1) m = fmaxf(m, __shfl_xor_sync(0xffffffffu, m, o));
                float e0 = expf(v0 - m), e1 = expf(v1 - m);
                float ssum = e0 + e1;
#pragma unroll
                for (int o = 16; o; o >>= 1) ssum += __shfl_xor_sync(0xffffffffu, ssum, o);
                float inv = 1.f / ssum;
                w_sh[lane] = e0 * inv;
                w_sh[lane + 32] = e1 * inv;
            }
            __syncthreads();
#pragma unroll
            for (int i = 0; i < H_ / 256; i++) {
                int k = tid + i * 256;
                const float* cp = contexts + (size_t)b * S_ * H_ + k;
                float a = 0.f;
#pragma unroll 8
                for (int s = 0; s < S_; s++) a = fmaf(w_sh[s], cp[(size_t)s * H_], a);
                g_ctx[b][k] = a;
            }
        }
        grid_bar();

        // ---- out[t][b][j] = tanh(b_out + W_out[:,:H].ctx + W_out[:,H:].h1) ----
        {
            unsigned long long acc[1] = {0ull};
            gemm_seg256<1>(sm, &g_ctx[0][0], W_out, 2 * H_,
                           blk * 8, 0, 1, acc, tid, wid, lane);
            gemm_seg256<1>(sm, &g_hbuf[cur][1][0][0], W_out + H_, 2 * H_,
                           blk * 8, 0, 1, acc, tid, wid, lane);
            const int j = blk * 8 + wid;
            out[(size_t)t * B_ * H_ + (size_t)lane * H_ + j] =
                tanhf(unpack_sum(acc[0]) + b_out[j]);
        }
        // no grid_bar here (safe: next writers of g_ctx/h1 are >=3 barriers away)
    }
}

// ===========================================================================
// pre0 (hoisted layer-0 input projection), 128-thread blocks — as in R5
// ===========================================================================
__device__ __forceinline__ void stage_xg128(float* xsb, const float* __restrict__ emb,
                                            const int* tok_sh, int k0, int tid) {
#pragma unroll
    for (int i = tid; i < B_ * (KT / 4); i += 128) {
        int b = i >> 5, k4 = i & 31;
        CPA16(su32(xsb + b * XST + k4 * 4),
              emb + (size_t)tok_sh[b] * H_ + k0 + k4 * 4);
    }
}
__device__ __forceinline__ void stage_w128(float* wsb, const float* __restrict__ Wk0,
                                           int rowBase, int tid) {
#pragma unroll
    for (int i = tid; i < 16 * (KT / 4); i += 128) {
        int rr = i >> 5, k4 = i & 31;
        int row = rowBase + (rr & 3) + (rr >> 2) * 4;
        CPA16(su32(wsb + rr * XST + k4 * 4), Wk0 + (size_t)row * H_ + k4 * 4);
    }
}

__global__ void __launch_bounds__(128) k_pre0(const int* __restrict__ tokens,
                                              const float* __restrict__ emb,
                                              const float* __restrict__ Wih0,
                                              const float* __restrict__ bih0,
                                              const float* __restrict__ bhh0) {
    extern __shared__ float sm[];
    __shared__ int tok_sh[B_];
    const int tid = threadIdx.x, wid = tid >> 5, lane = tid & 31;
    const int t = blockIdx.y;
    const int j0 = blockIdx.x * 16;
    if (tid < B_) tok_sh[tid] = tokens[t * B_ + tid];
    __syncthreads();

    float* xs = sm;
    float* ws = sm + 2 * XB;
    unsigned long long acc[4] = {0ull, 0ull, 0ull, 0ull};

    stage_xg128(xs, emb, tok_sh, 0, tid);
    stage_w128(ws, Wih0, j0, tid);
    CP_COMMIT();
    constexpr int NT = H_ / KT;
    for (int tt = 0; tt < NT; tt++) {
        const int cb = tt & 1;
        if (tt + 1 < NT) {
            const int nb = cb ^ 1;
            stage_xg128(xs + nb * XB, emb, tok_sh, (tt + 1) * KT, tid);
            stage_w128(ws + nb * WB128, Wih0 + (size_t)(tt + 1) * KT, j0, tid);
            CP_COMMIT();
            asm volatile("cp.async.wait_group 1;" ::: "memory");
        } else {
            asm volatile("cp.async.wait_group 0;" ::: "memory");
        }
        __syncthreads();
        {
            const float* xp = xs + cb * XB + lane * XST;
            const float* wp = ws + cb * WB128 + wid * 4 * XST;
#pragma unroll 4
            for (int k = 0; k < KT; k += 4) {
                ulonglong2 xv = *(const ulonglong2*)(xp + k);
#pragma unroll
                for (int r = 0; r < 4; r++) {
                    ulonglong2 wv = *(const ulonglong2*)(wp + r * XST + k);
                    asm("fma.rn.f32x2 %0, %1, %2, %0;" : "+l"(acc[r]) : "l"(xv.x), "l"(wv.x));
                    asm("fma.rn.f32x2 %0, %1, %2, %0;" : "+l"(acc[r]) : "l"(xv.y), "l"(wv.y));
                }
            }
        }
        __syncthreads();
    }
#pragma unroll
    for (int r = 0; r < 4; r++) {
        int j = j0 + wid * 4 + r;   // rr = wid*4+r -> row = (rr&3) + (rr>>2)*4 = r + wid*4
        g_pre0[((size_t)t * G_ + j) * B_ + lane] =
            unpack_sum(acc[r]) + bih0[j] + bhh0[j];
    }
}

// ---------------------------------------------------------------------------
extern "C" void kernel_launch(void* const* d_in, const int* in_sizes, int n_in,
                              void* d_out, int out_size) {
    const int*   tokens   = (const int*)d_in[0];
    const float* h0       = (const float*)d_in[1];
    const float* c0       = (const float*)d_in[2];
    const float* contexts = (const float*)d_in[3];
    const float* emb      = (const float*)d_in[4];
    const float* W_ih     = (const float*)d_in[5];
    const float* W_hh     = (const float*)d_in[6];
    const float* b_ih     = (const float*)d_in[7];
    const float* b_hh     = (const float*)d_in[8];
    const float* W_in     = (const float*)d_in[9];
    const float* b_in     = (const float*)d_in[10];
    const float* W_out    = (const float*)d_in[11];
    const float* b_out    = (const float*)d_in[12];
    float* out = (float*)d_out;

    cudaFuncSetAttribute(k_pre0,  cudaFuncAttributeMaxDynamicSharedMemorySize, SMEM_PRE0);
    cudaFuncSetAttribute(k_steps, cudaFuncAttributeMaxDynamicSharedMemorySize, SMEM_STEPS);

    const size_t stateBytes = (size_t)L_ * B_ * H_ * sizeof(float);

    // init state: h -> hbuf[1] (prev of t=0), c -> g_c
    cudaMemcpyToSymbolAsync(g_hbuf, h0, stateBytes, stateBytes,
                            cudaMemcpyDeviceToDevice, 0);
    cudaMemcpyToSymbolAsync(g_c, c0, stateBytes, 0, cudaMemcpyDeviceToDevice, 0);

    // hoisted layer-0 input projection for all timesteps
    k_pre0<<<dim3(G_ / 16, T_), 128, SMEM_PRE0>>>(tokens, emb, W_ih, b_ih, b_hh);

    const float* Wih1 = W_ih + (size_t)G_ * H_;
    const float* Whh1 = W_hh + (size_t)G_ * H_;
    const float* bih1 = b_ih + G_;
    const float* bhh1 = b_hh + G_;

    // entire recurrence in ONE persistent kernel
    k_steps<<<NBLK, 256, SMEM_STEPS>>>(W_hh, Wih1, Whh1, bih1, bhh1,
                                       W_in, b_in, W_out, b_out, contexts, out);

    // hT (lives in hbuf[1] since (T-1)&1 == 1), then cT
    cudaMemcpyFromSymbolAsync(out + (size_t)T_ * B_ * H_, g_hbuf, stateBytes,
                              stateBytes, cudaMemcpyDeviceToDevice, 0);
    cudaMemcpyFromSymbolAsync(out + (size_t)T_ * B_ * H_ + (size_t)L_ * B_ * H_,
                              g_c, stateBytes, 0, cudaMemcpyDeviceToDevice, 0);
}

// round 8
// speedup vs baseline: 1.4423x; 1.4423x over previous
#include <cuda_runtime.h>
#include <math.h>

constexpr int H_ = 1024, G_ = 4096, B_ = 32, T_ = 64, S_ = 64, L_ = 2;
constexpr int KP  = 256;           // k per pass
constexpr int XST = 268;           // smem row stride (floats)
constexpr int BUF = 8592;          // floats per buffer (32*268 + skew pad)
constexpr int SMEM_BYTES = 4 * BUF * 4;   // 137472 B
constexpr int NBLK = 128;          // persistent grid

// Scratch (device globals)
__device__ float g_pre0[(size_t)T_ * G_ * B_];   // [t][j][b]
__device__ float g_hbuf[2][L_][B_][H_];
__device__ float g_c[L_][B_][H_];
__device__ float g_gamma[B_][H_];
__device__ float g_ctx[B_][H_];
__device__ unsigned g_bar_cnt;
__device__ volatile unsigned g_bar_gen;

__device__ __forceinline__ float sigf(float x) { return 1.f / (1.f + expf(-x)); }
__device__ __forceinline__ unsigned su32(const void* p) {
    return (unsigned)__cvta_generic_to_shared(p);
}
__device__ __forceinline__ float unpack_sum(unsigned long long u) {
    float lo, hi;
    asm("mov.b64 {%0,%1}, %2;" : "=f"(lo), "=f"(hi) : "l"(u));
    return lo + hi;
}
#define FMA2(a, x, w) asm("fma.rn.f32x2 %0, %1, %2, %0;" : "+l"(a) : "l"(x), "l"(w))

__device__ __forceinline__ void mb_init(unsigned long long* m) {
    asm volatile("mbarrier.init.shared.b64 [%0], 1;" :: "r"(su32(m)) : "memory");
}
__device__ __forceinline__ void mb_expect(unsigned mb, unsigned bytes) {
    asm volatile("mbarrier.arrive.expect_tx.shared.b64 _, [%0], %1;"
                 :: "r"(mb), "r"(bytes) : "memory");
}
__device__ __forceinline__ void mb_wait(unsigned mb, unsigned par) {
    asm volatile(
        "{\n\t.reg .pred P;\n\tW1_%=:\n\t"
        "mbarrier.try_wait.parity.acquire.cta.shared::cta.b64 P, [%0], %1, 0x989680;\n\t"
        "@P bra.uni W2_%=;\n\tbra.uni W1_%=;\n\tW2_%=:\n\t}"
        :: "r"(mb), "r"(par) : "memory");
}
__device__ __forceinline__ void bulk1k(unsigned dst, const float* src, unsigned mb) {
    asm volatile(
        "cp.async.bulk.shared::cta.global.mbarrier::complete_tx::bytes [%0], [%1], 1024, [%2];"
        :: "r"(dst), "l"(src), "r"(mb) : "memory");
}

__device__ __forceinline__ void grid_bar() {
    __syncthreads();
    if (threadIdx.x == 0) {
        __threadfence();
        unsigned gen = g_bar_gen;
        if (atomicInc(&g_bar_cnt, NBLK - 1) == NBLK - 1) g_bar_gen = gen + 1;
        else while (g_bar_gen == gen) __nanosleep(32);
        __threadfence();
    }
    __syncthreads();
}

__device__ __forceinline__ int skw(int r) { return ((r >> 3) & 3) * 4; }

// ---------------------------------------------------------------------------
// Stage one pass into (xb, wb): 32 x-rows + nw w-rows, 1KB bulk copies.
// Weight smem row r -> global row j0 + (r&7) + (r>>3)*GS.
// __syncthreads inside doubles as the producer/consumer WAR barrier.
// ---------------------------------------------------------------------------
template <bool GATHER>
__device__ __forceinline__ void stage(int nw, float* xb, float* wb, unsigned mb,
                                      const float* __restrict__ X, const int* toks,
                                      const float* __restrict__ W, size_t ldw,
                                      int j0, int GS, int k0, int tid) {
    if (tid == 0) mb_expect(mb, (unsigned)(32 + nw) * 1024u);
    __syncthreads();
    if (tid < 32) {
        const float* src = GATHER ? X + (size_t)toks[tid] * H_ + k0
                                  : X + (size_t)tid * H_ + k0;
        bulk1k(su32(xb + tid * XST + skw(tid)), src, mb);
    } else if (tid < 32 + nw) {
        int r = tid - 32;
        bulk1k(su32(wb + r * XST + skw(r)),
               W + (size_t)(j0 + (r & 7) + (r >> 3) * GS) * ldw + k0, mb);
    }
}

// ---------------------------------------------------------------------------
// 32-row GEMM (cells, pre0): warp = (ks = wid&3 k-slice of 64, rh = wid>>2 row half)
// thread tile = 8 rows x 2 batches. acc[16] f32x2 (k-paired).
// ---------------------------------------------------------------------------
template <bool GATHER>
__device__ __forceinline__ void gemm32(float* sm, const unsigned* mbs, unsigned* ph,
                                       const float* __restrict__ X, const int* toks,
                                       const float* __restrict__ W, size_t ldw,
                                       int j0, int GS, int NPK,
                                       unsigned long long* acc,
                                       int tid, int wid, int lane) {
    float* xb[2] = {sm, sm + 2 * BUF};
    float* wb[2] = {sm + BUF, sm + 3 * BUF};
    const int ks = wid & 3, rh = wid >> 2;
    const int bp = lane & 15, rg = lane >> 4;
    const int R0 = rh * 16 + rg * 8;
    stage<GATHER>(32, xb[0], wb[0], mbs[0], X, toks, W, ldw, j0, GS, 0, tid);
    stage<GATHER>(32, xb[1], wb[1], mbs[1], X, toks, W, ldw, j0, GS, KP, tid);
    for (int p = 0; p < NPK; p++) {
        int s = p & 1;
        mb_wait(mbs[s], ph[s] & 1);
        ph[s]++;
        const float* xp0 = xb[s] + (2 * bp) * XST + skw(2 * bp) + ks * 64;
        const float* wp  = wb[s] + R0 * XST + skw(R0) + ks * 64;
#pragma unroll 2
        for (int kq = 0; kq < 64; kq += 4) {
            ulonglong2 x0 = *(const ulonglong2*)(xp0 + kq);
            ulonglong2 x1 = *(const ulonglong2*)(xp0 + XST + kq);
#pragma unroll
            for (int r = 0; r < 8; r++) {
                ulonglong2 wv = *(const ulonglong2*)(wp + r * XST + kq);
                FMA2(acc[2 * r],     x0.x, wv.x); FMA2(acc[2 * r],     x0.y, wv.y);
                FMA2(acc[2 * r + 1], x1.x, wv.x); FMA2(acc[2 * r + 1], x1.y, wv.y);
            }
        }
        if (p + 2 < NPK)
            stage<GATHER>(32, xb[s], wb[s], mbs[s], X, toks, W, ldw, j0, GS,
                          (p + 2) * KP, tid);
    }
}

// ---------------------------------------------------------------------------
// 8-row GEMM (gamma/out): warp = k-slice of 32 (wid), lane = (kk = lane>>4
// sub-slice of 16, bp = lane&15). thread tile = 8 rows x 2 batches.
// ---------------------------------------------------------------------------
__device__ __forceinline__ void gemm8(float* sm, const unsigned* mbs, unsigned* ph,
                                      const float* __restrict__ X,
                                      const float* __restrict__ W, size_t ldw,
                                      int j0, int NPK, unsigned long long* acc,
                                      int tid, int wid, int lane) {
    float* xb[2] = {sm, sm + 2 * BUF};
    float* wb[2] = {sm + BUF, sm + 3 * BUF};
    const int bp = lane & 15, kk = lane >> 4;
    stage<false>(8, xb[0], wb[0], mbs[0], X, nullptr, W, ldw, j0, 8, 0, tid);
    stage<false>(8, xb[1], wb[1], mbs[1], X, nullptr, W, ldw, j0, 8, KP, tid);
    for (int p = 0; p < NPK; p++) {
        int s = p & 1;
        mb_wait(mbs[s], ph[s] & 1);
        ph[s]++;
        const int ko = wid * 32 + kk * 16;
        const float* xp0 = xb[s] + (2 * bp) * XST + skw(2 * bp) + ko;
        const float* wp  = wb[s] + ko;   // rows 0..7 -> skw = 0
#pragma unroll
        for (int kq = 0; kq < 16; kq += 4) {
            ulonglong2 x0 = *(const ulonglong2*)(xp0 + kq);
            ulonglong2 x1 = *(const ulonglong2*)(xp0 + XST + kq);
#pragma unroll
            for (int r = 0; r < 8; r++) {
                ulonglong2 wv = *(const ulonglong2*)(wp + r * XST + kq);
                FMA2(acc[2 * r],     x0.x, wv.x); FMA2(acc[2 * r],     x0.y, wv.y);
                FMA2(acc[2 * r + 1], x1.x, wv.x); FMA2(acc[2 * r + 1], x1.y, wv.y);
            }
        }
        if (p + 2 < NPK)
            stage<false>(8, xb[s], wb[s], mbs[s], X, nullptr, W, ldw, j0, 8,
                         (p + 2) * KP, tid);
    }
}

// Partial-sum reductions via smem (reuses buffer 0 region after compute done)
__device__ __forceinline__ void red_write32(float* red, const unsigned long long* acc,
                                            int wid, int lane) {
    const int ks = wid & 3, rh = wid >> 2, bp = lane & 15, rg = lane >> 4;
    const int R0 = rh * 16 + rg * 8;
#pragma unroll
    for (int r = 0; r < 8; r++) {
        float2 v = make_float2(unpack_sum(acc[2 * r]), unpack_sum(acc[2 * r + 1]));
        *(float2*)&red[ks * 1024 + (R0 + r) * 32 + 2 * bp] = v;
    }
}
__device__ __forceinline__ float red_sum32(const float* red, int row, int b) {
    return red[row * 32 + b] + red[1024 + row * 32 + b] +
           red[2048 + row * 32 + b] + red[3072 + row * 32 + b];
}
__device__ __forceinline__ void red_write8(float* red, const unsigned long long* acc,
                                           int wid, int lane) {
    const int bp = lane & 15, kk = lane >> 4;
    const int sl = wid * 2 + kk;
#pragma unroll
    for (int r = 0; r < 8; r++) {
        float2 v = make_float2(unpack_sum(acc[2 * r]), unpack_sum(acc[2 * r + 1]));
        *(float2*)&red[sl * 256 + r * 32 + 2 * bp] = v;
    }
}
__device__ __forceinline__ float red_sum8(const float* red, int row, int b) {
    float s = 0.f;
#pragma unroll
    for (int i = 0; i < 16; i++) s += red[i * 256 + row * 32 + b];
    return s;
}

// ===========================================================================
// Persistent step kernel. grid NBLK x 256.
// Per step: cell0 |BAR| cell1 |BAR| gamma |BAR| attn |BAR| out
// ===========================================================================
__global__ void __launch_bounds__(256, 1) k_steps(const float* __restrict__ Whh0,
                                                  const float* __restrict__ Wih1,
                                                  const float* __restrict__ Whh1,
                                                  const float* __restrict__ bih1,
                                                  const float* __restrict__ bhh1,
                                                  const float* __restrict__ W_in,
                                                  const float* __restrict__ b_in,
                                                  const float* __restrict__ W_out,
                                                  const float* __restrict__ b_out,
                                                  const float* __restrict__ contexts,
                                                  float* __restrict__ out) {
    extern __shared__ float sm[];
    __shared__ unsigned long long mbar[2];
    __shared__ float gs[H_];
    __shared__ float w_sh[S_];
    const int tid = threadIdx.x, wid = tid >> 5, lane = tid & 31;
    const int blk = blockIdx.x;
    const int jl = tid >> 5, b = tid & 31;
    const int j = blk * 8 + jl;

    if (tid == 0) { mb_init(&mbar[0]); mb_init(&mbar[1]); }
    __syncthreads();
    unsigned mbs[2] = {su32(&mbar[0]), su32(&mbar[1])};
    unsigned ph[2] = {0u, 0u};

    for (int t = 0; t < T_; t++) {
        const int cur = t & 1;

        // ---- cell0 ----
        {
            unsigned long long acc[16] = {};
            gemm32<false>(sm, mbs, ph, &g_hbuf[1 - cur][0][0][0], nullptr,
                          Whh0, H_, blk * 8, H_, 4, acc, tid, wid, lane);
            __syncthreads();
            red_write32(sm, acc, wid, lane);
            __syncthreads();
            const float* pre = g_pre0 + (size_t)t * G_ * B_;
            float v[4];
#pragma unroll
            for (int g = 0; g < 4; g++)
                v[g] = red_sum32(sm, g * 8 + jl, b) + pre[(size_t)(g * H_ + j) * B_ + b];
            float c1 = sigf(v[1]) * g_c[0][b][j] + sigf(v[0]) * tanhf(v[2]);
            g_c[0][b][j] = c1;
            g_hbuf[cur][0][b][j] = sigf(v[3]) * tanhf(c1);
        }
        grid_bar();

        // ---- cell1 ----
        {
            unsigned long long acc[16] = {};
            gemm32<false>(sm, mbs, ph, &g_hbuf[cur][0][0][0], nullptr,
                          Wih1, H_, blk * 8, H_, 4, acc, tid, wid, lane);
            gemm32<false>(sm, mbs, ph, &g_hbuf[1 - cur][1][0][0], nullptr,
                          Whh1, H_, blk * 8, H_, 4, acc, tid, wid, lane);
            __syncthreads();
            red_write32(sm, acc, wid, lane);
            __syncthreads();
            float v[4];
#pragma unroll
            for (int g = 0; g < 4; g++)
                v[g] = red_sum32(sm, g * 8 + jl, b) + bih1[g * H_ + j] + bhh1[g * H_ + j];
            float c1 = sigf(v[1]) * g_c[1][b][j] + sigf(v[0]) * tanhf(v[2]);
            g_c[1][b][j] = c1;
            g_hbuf[cur][1][b][j] = sigf(v[3]) * tanhf(c1);
        }
        grid_bar();

        // ---- gamma ----
        {
            unsigned long long acc[16] = {};
            gemm8(sm, mbs, ph, &g_hbuf[cur][1][0][0], W_in, H_, blk * 8, 4,
                  acc, tid, wid, lane);
            __syncthreads();
            red_write8(sm, acc, wid, lane);
            __syncthreads();
            g_gamma[b][j] = red_sum8(sm, jl, b) + b_in[j];
        }
        grid_bar();

        // ---- attention (blocks 0..31) ----
        if (blk < B_) {
            const int bb = blk;
            for (int i = tid; i < H_; i += 256) gs[i] = g_gamma[bb][i];
            __syncthreads();
#pragma unroll
            for (int si = 0; si < S_ / 8; si++) {
                int s = wid * (S_ / 8) + si;
                const float* cp = contexts + ((size_t)bb * S_ + s) * H_;
                float a = 0.f;
                for (int k = lane; k < H_; k += 32) a = fmaf(cp[k], gs[k], a);
#pragma unroll
                for (int o = 16; o; o >>= 1) a += __shfl_xor_sync(0xffffffffu, a, o);
                if (lane == 0) w_sh[s] = a;
            }
            __syncthreads();
            if (wid == 0) {
                float v0 = w_sh[lane], v1 = w_sh[lane + 32];
                float m = fmaxf(v0, v1);
#pragma unroll
                for (int o = 16; o; o >>= 1) m = fmaxf(m, __shfl_xor_sync(0xffffffffu, m, o));
                float e0 = expf(v0 - m), e1 = expf(v1 - m);
                float ssum = e0 + e1;
#pragma unroll
                for (int o = 16; o; o >>= 1) ssum += __shfl_xor_sync(0xffffffffu, ssum, o);
                float inv = 1.f / ssum;
                w_sh[lane] = e0 * inv;
                w_sh[lane + 32] = e1 * inv;
            }
            __syncthreads();
#pragma unroll
            for (int i = 0; i < H_ / 256; i++) {
                int k = tid + i * 256;
                const float* cp = contexts + (size_t)bb * S_ * H_ + k;
                float a = 0.f;
#pragma unroll 8
                for (int s = 0; s < S_; s++) a = fmaf(w_sh[s], cp[(size_t)s * H_], a);
                g_ctx[bb][k] = a;
            }
        }
        grid_bar();

        // ---- out ----
        {
            unsigned long long acc[16] = {};
            gemm8(sm, mbs, ph, &g_ctx[0][0], W_out, 2 * H_, blk * 8, 4,
                  acc, tid, wid, lane);
            gemm8(sm, mbs, ph, &g_hbuf[cur][1][0][0], W_out + H_, 2 * H_, blk * 8, 4,
                  acc, tid, wid, lane);
            __syncthreads();
            red_write8(sm, acc, wid, lane);
            __syncthreads();
            out[(size_t)t * B_ * H_ + (size_t)b * H_ + j] =
                tanhf(red_sum8(sm, jl, b) + b_out[j]);
        }
        // no grid_bar: out's inputs are protected by the next step's barriers
    }
}

// ===========================================================================
// pre0: grid (G/32, T) x 256. Same 32-row GEMM with embedding gather, GS=8
// (smem row rr <-> global row j0+rr).
// ===========================================================================
__global__ void __launch_bounds__(256, 1) k_pre0(const int* __restrict__ tokens,
                                                 const float* __restrict__ emb,
                                                 const float* __restrict__ Wih0,
                                                 const float* __restrict__ bih0,
                                                 const float* __restrict__ bhh0) {
    extern __shared__ float sm[];
    __shared__ unsigned long long mbar[2];
    __shared__ int toks[B_];
    const int tid = threadIdx.x, wid = tid >> 5, lane = tid & 31;
    const int t = blockIdx.y;
    const int j0 = blockIdx.x * 32;

    if (tid == 0) { mb_init(&mbar[0]); mb_init(&mbar[1]); }
    if (tid < B_) toks[tid] = tokens[t * B_ + tid];
    __syncthreads();
    unsigned mbs[2] = {su32(&mbar[0]), su32(&mbar[1])};
    unsigned ph[2] = {0u, 0u};

    unsigned long long acc[16] = {};
    gemm32<true>(sm, mbs, ph, emb, toks, Wih0, H_, j0, 8, 4, acc, tid, wid, lane);
    __syncthreads();
    red_write32(sm, acc, wid, lane);
    __syncthreads();

    const int jl = tid >> 5, b = tid & 31;
#pragma unroll
    for (int i = 0; i < 4; i++) {
        int row = jl + i * 8;
        int jj = j0 + row;
        g_pre0[((size_t)t * G_ + jj) * B_ + b] =
            red_sum32(sm, row, b) + bih0[jj] + bhh0[jj];
    }
}

// ---------------------------------------------------------------------------
extern "C" void kernel_launch(void* const* d_in, const int* in_sizes, int n_in,
                              void* d_out, int out_size) {
    const int*   tokens   = (const int*)d_in[0];
    const float* h0       = (const float*)d_in[1];
    const float* c0       = (const float*)d_in[2];
    const float* contexts = (const float*)d_in[3];
    const float* emb      = (const float*)d_in[4];
    const float* W_ih     = (const float*)d_in[5];
    const float* W_hh     = (const float*)d_in[6];
    const float* b_ih     = (const float*)d_in[7];
    const float* b_hh     = (const float*)d_in[8];
    const float* W_in     = (const float*)d_in[9];
    const float* b_in     = (const float*)d_in[10];
    const float* W_out    = (const float*)d_in[11];
    const float* b_out    = (const float*)d_in[12];
    float* out = (float*)d_out;

    cudaFuncSetAttribute(k_pre0,  cudaFuncAttributeMaxDynamicSharedMemorySize, SMEM_BYTES);
    cudaFuncSetAttribute(k_steps, cudaFuncAttributeMaxDynamicSharedMemorySize, SMEM_BYTES);

    const size_t stateBytes = (size_t)L_ * B_ * H_ * sizeof(float);

    // init state: h -> hbuf[1] (prev of t=0), c -> g_c
    cudaMemcpyToSymbolAsync(g_hbuf, h0, stateBytes, stateBytes,
                            cudaMemcpyDeviceToDevice, 0);
    cudaMemcpyToSymbolAsync(g_c, c0, stateBytes, 0, cudaMemcpyDeviceToDevice, 0);

    // hoisted layer-0 input projection for all timesteps
    k_pre0<<<dim3(G_ / 32, T_), 256, SMEM_BYTES>>>(tokens, emb, W_ih, b_ih, b_hh);

    const float* Wih1 = W_ih + (size_t)G_ * H_;
    const float* Whh1 = W_hh + (size_t)G_ * H_;
    const float* bih1 = b_ih + G_;
    const float* bhh1 = b_hh + G_;

    // entire recurrence in ONE persistent kernel
    k_steps<<<NBLK, 256, SMEM_BYTES>>>(W_hh, Wih1, Whh1, bih1, bhh1,
                                       W_in, b_in, W_out, b_out, contexts, out);

    // hT (in hbuf[1] since (T-1)&1 == 1), then cT
    cudaMemcpyFromSymbolAsync(out + (size_t)T_ * B_ * H_, g_hbuf, stateBytes,
                              stateBytes, cudaMemcpyDeviceToDevice, 0);
    cudaMemcpyFromSymbolAsync(out + (size_t)T_ * B_ * H_ + (size_t)L_ * B_ * H_,
                              g_c, stateBytes, 0, cudaMemcpyDeviceToDevice, 0);
}